// round 12
// baseline (speedup 1.0000x reference)
#include <cuda_runtime.h>
#include <cstdint>

#define MM 512
#define NN 1024
#define WR 16
#define BB 4096
#define BPB 8            // batches per block (2 warps, 8 lanes per batch)
#define STRIDE 1028      // padded floats per batch row in smem

#define ABSM 0x7FFFFFFFu
#define SGNM 0x80000000u
#define FULL 0xFFFFFFFFu

// Split c2v state (80 MB total, L2-resident):
//  g_m[cn*BB + batch]          = {m1c bits, m2c bits}           (8 B, lane 0)
//  g_s[(cn*BB + batch)*8 + li] = {flip_lo | flip_hi<<1 | eq_lo<<2 | eq_hi<<3}
// Edge amp = eq ? m2c : m1c;  c2v sign = flip bit.
__device__ uint2 g_m[MM * BB];
__device__ unsigned g_s[MM * BB * 8];

// Prefetch slot S for global step T. Unpacks this lane's two edges off-chain.
#define PREFETCH(S, T) do {                                                  \
    cn##S  = __ldg(&cn_order[tm]); if (++tm == MM) tm = 0;                   \
    ilo##S = __ldg(&H[cn##S * WR + li]);                                     \
    ihi##S = __ldg(&H[cn##S * WR + li + 8]);                                 \
    if ((T) < MM) {                                                          \
        clo##S = 0.0f; chi##S = 0.0f;                                        \
    } else {                                                                 \
        const unsigned sel = g_s[(cn##S * BB + batch) * 8 + li];             \
        const uint2 mm = g_m[cn##S * BB + batch];                            \
        const unsigned alo_ = (sel & 4u) ? mm.y : mm.x;                      \
        const unsigned ahi_ = (sel & 8u) ? mm.y : mm.x;                      \
        clo##S = __uint_as_float(alo_ | (sel << 31));                        \
        chi##S = __uint_as_float(ahi_ | ((sel << 30) & SGNM));               \
    }                                                                        \
} while (0)

// One check-node update: 2 edges/lane, 3-stage butterfly, 8 collective units.
#define STEP(S) do {                                                         \
    const float tlo = vn[ilo##S] - clo##S;                                   \
    const float thi = vn[ihi##S] - chi##S;                                   \
    const unsigned ulo = __float_as_uint(tlo);                               \
    const unsigned uhi = __float_as_uint(thi);                               \
    const float alo = __uint_as_float(ulo & ABSM);                           \
    const float ahi = __uint_as_float(uhi & ABSM);                           \
    /* single ballot: per-lane XOR of the two edge signs -> group parity */  \
    const unsigned bx = __ballot_sync(FULL, ((ulo ^ uhi) & SGNM) != 0u);     \
    float m1 = fminf(alo, ahi);                                              \
    float m2 = fmaxf(alo, ahi);                                              \
    {   const float o1 = __shfl_xor_sync(FULL, m1, 1);                       \
        const float o2 = __shfl_xor_sync(FULL, m2, 1);                       \
        m2 = fminf(fmaxf(m1, o1), fminf(m2, o2)); m1 = fminf(m1, o1); }      \
    {   const float o1 = __shfl_xor_sync(FULL, m1, 2);                       \
        const float o2 = __shfl_xor_sync(FULL, m2, 2);                       \
        m2 = fminf(fmaxf(m1, o1), fminf(m2, o2)); m1 = fminf(m1, o1); }      \
    {   const float o1 = __shfl_xor_sync(FULL, m1, 4);                       \
        const float o2 = __shfl_xor_sync(FULL, m2, 4);                       \
        m2 = fminf(fmaxf(m1, o1), fminf(m2, o2)); m1 = fminf(m1, o1); }      \
    const unsigned par = (unsigned)__popc((bx >> sh) & 0xFFu) & 1u;          \
    const unsigned par31 = par << 31;                                        \
    const float m1c = fminf(m1, 20.0f);                                      \
    const float m2c = fminf(m2, 20.0f);                                      \
    const unsigned eqlo = (alo == m1) ? 1u : 0u;                             \
    const unsigned eqhi = (ahi == m1) ? 1u : 0u;                             \
    const float amplo = eqlo ? m2c : m1c;                                    \
    const float amphi = eqhi ? m2c : m1c;                                    \
    const float cwlo = __uint_as_float(__float_as_uint(amplo)                \
                                       | ((par31 ^ ulo) & SGNM));            \
    const float cwhi = __uint_as_float(__float_as_uint(amphi)                \
                                       | ((par31 ^ uhi) & SGNM));            \
    vn[ilo##S] = tlo + cwlo;                                                 \
    vn[ihi##S] = thi + cwhi;                                                 \
    /* per-lane state store (coalesced 128 B per warp) */                    \
    const unsigned flo = (__float_as_uint(cwlo) >> 31);                      \
    const unsigned fhi = (__float_as_uint(cwhi) >> 31);                      \
    g_s[(cn##S * BB + batch) * 8 + li] =                                     \
        flo | (fhi << 1) | (eqlo << 2) | (eqhi << 3);                        \
    if (li == 0)                                                             \
        g_m[cn##S * BB + batch] =                                            \
            make_uint2(__float_as_uint(m1c), __float_as_uint(m2c));          \
    __syncwarp();                                                            \
} while (0)

__global__ __launch_bounds__(64)
void ldpc_layered_ms_kernel(const float* __restrict__ llr,
                            const int*   __restrict__ H,
                            const int*   __restrict__ iters_p,
                            const int*   __restrict__ cn_order,
                            float*       __restrict__ out)
{
    __shared__ float sh_vn[BPB * STRIDE];

    const int tid   = threadIdx.x;              // 0..63
    const int lane  = tid & 31;
    const int li    = lane & 7;                 // lane within 8-lane group
    const int sh    = lane & 24;                // group's bit offset in ballots
    const int g     = tid >> 3;                 // local batch 0..7
    const int batch = blockIdx.x * BPB + g;

    float* vn = sh_vn + g * STRIDE;

    // Load channel LLRs (float4 per lane; 8 lanes cover 32 floats per pass).
    const float4* src = (const float4*)(llr + (size_t)batch * NN);
    #pragma unroll 4
    for (int k = li; k < NN / 4; k += 8) {
        const float4 v = __ldg(src + k);
        vn[4*k + 0] = v.x;  vn[4*k + 1] = v.y;
        vn[4*k + 2] = v.z;  vn[4*k + 3] = v.w;
    }
    __syncwarp();

    const int iters = *iters_p;
    const int total = iters * MM;               // 2560, even

    // ---- 2-deep software pipeline ----
    int cnA, cnB, iloA, ihiA, iloB, ihiB;
    float cloA, chiA, cloB, chiB;
    int tm = 0;
    PREFETCH(A, 0);
    PREFETCH(B, 1);

    for (int t = 0; t < total; t += 2) {
        STEP(A); PREFETCH(A, t + 2);   // cn_{t+2} distinct in window: safe vs stores
        STEP(B); PREFETCH(B, t + 3);
    }

    // Hard decision output.
    float4* dst = (float4*)(out + (size_t)batch * NN);
    #pragma unroll 4
    for (int k = li; k < NN / 4; k += 8) {
        float4 r;
        r.x = (vn[4*k + 0] < 0.f) ? 1.f : 0.f;
        r.y = (vn[4*k + 1] < 0.f) ? 1.f : 0.f;
        r.z = (vn[4*k + 2] < 0.f) ? 1.f : 0.f;
        r.w = (vn[4*k + 3] < 0.f) ? 1.f : 0.f;
        dst[k] = r;
    }
}

extern "C" void kernel_launch(void* const* d_in, const int* in_sizes, int n_in,
                              void* d_out, int out_size)
{
    const float* llr      = (const float*)d_in[0];   // channel_llr [4096,1024] f32
    const int*   H        = (const int*)  d_in[1];   // H_compact   [512,16]    i32
    const int*   iters_p  = (const int*)  d_in[2];   // iters scalar
    const int*   cn_order = (const int*)  d_in[3];   // cn_order    [512]       i32
    float*       out      = (float*)d_out;

    (void)in_sizes; (void)n_in; (void)out_size;

    ldpc_layered_ms_kernel<<<BB / BPB, 64>>>(llr, H, iters_p, cn_order, out);
}

// round 13
// speedup vs baseline: 1.3496x; 1.3496x over previous
#include <cuda_runtime.h>
#include <cstdint>

#define MM 512
#define NN 1024
#define WR 16
#define BB 4096
#define BPB 8            // batches per block (2 warps, 8 lanes per batch)
#define STRIDE 1028      // padded floats per batch row in smem

#define ABSM 0x7FFFFFFFu
#define SGNM 0x80000000u
#define FULL 0xFFFFFFFFu

// Split c2v state (32 MB total -> fully L2-resident):
//  g_m[cn*BB + batch]          = {m1c bits, m2c bits}  (8 B, written by lane 0)
//  g_s[(cn*BB + batch)*8 + li] = flip_lo | flip_hi<<1 | eq_lo<<2 | eq_hi<<3 (1 B)
// Edge amp = eq ? m2c : m1c;  c2v sign = flip bit.
__device__ uint2 g_m[MM * BB];
__device__ unsigned char g_s[MM * BB * 8];

// Prefetch slot S for global step T. Unpacks this lane's two edges off-chain.
#define PREFETCH(S, T) do {                                                  \
    cn##S  = __ldg(&cn_order[tm]); if (++tm == MM) tm = 0;                   \
    ilo##S = __ldg(&H[cn##S * WR + li]);                                     \
    ihi##S = __ldg(&H[cn##S * WR + li + 8]);                                 \
    if ((T) < MM) {                                                          \
        clo##S = 0.0f; chi##S = 0.0f;                                        \
    } else {                                                                 \
        const unsigned sel = (unsigned)g_s[(cn##S * BB + batch) * 8 + li];   \
        const uint2 mm = g_m[cn##S * BB + batch];                            \
        const unsigned alo_ = (sel & 4u) ? mm.y : mm.x;                      \
        const unsigned ahi_ = (sel & 8u) ? mm.y : mm.x;                      \
        clo##S = __uint_as_float(alo_ | (sel << 31));                        \
        chi##S = __uint_as_float(ahi_ | ((sel << 30) & SGNM));               \
    }                                                                        \
} while (0)

// One check-node update: 2 edges/lane, 3-stage butterfly, 8 collective units.
#define STEP(S) do {                                                         \
    const float tlo = vn[ilo##S] - clo##S;                                   \
    const float thi = vn[ihi##S] - chi##S;                                   \
    const unsigned ulo = __float_as_uint(tlo);                               \
    const unsigned uhi = __float_as_uint(thi);                               \
    const float alo = __uint_as_float(ulo & ABSM);                           \
    const float ahi = __uint_as_float(uhi & ABSM);                           \
    /* single ballot: per-lane XOR of the two edge signs -> group parity */  \
    const unsigned bx = __ballot_sync(FULL, ((ulo ^ uhi) & SGNM) != 0u);     \
    float m1 = fminf(alo, ahi);                                              \
    float m2 = fmaxf(alo, ahi);                                              \
    {   const float o1 = __shfl_xor_sync(FULL, m1, 1);                       \
        const float o2 = __shfl_xor_sync(FULL, m2, 1);                       \
        m2 = fminf(fmaxf(m1, o1), fminf(m2, o2)); m1 = fminf(m1, o1); }      \
    {   const float o1 = __shfl_xor_sync(FULL, m1, 2);                       \
        const float o2 = __shfl_xor_sync(FULL, m2, 2);                       \
        m2 = fminf(fmaxf(m1, o1), fminf(m2, o2)); m1 = fminf(m1, o1); }      \
    {   const float o1 = __shfl_xor_sync(FULL, m1, 4);                       \
        const float o2 = __shfl_xor_sync(FULL, m2, 4);                       \
        m2 = fminf(fmaxf(m1, o1), fminf(m2, o2)); m1 = fminf(m1, o1); }      \
    const unsigned par = (unsigned)__popc((bx >> sh) & 0xFFu) & 1u;          \
    const unsigned par31 = par << 31;                                        \
    const float m1c = fminf(m1, 20.0f);                                      \
    const float m2c = fminf(m2, 20.0f);                                      \
    const unsigned eqlo = (alo == m1) ? 1u : 0u;                             \
    const unsigned eqhi = (ahi == m1) ? 1u : 0u;                             \
    const float amplo = eqlo ? m2c : m1c;                                    \
    const float amphi = eqhi ? m2c : m1c;                                    \
    const float cwlo = __uint_as_float(__float_as_uint(amplo)                \
                                       | ((par31 ^ ulo) & SGNM));            \
    const float cwhi = __uint_as_float(__float_as_uint(amphi)                \
                                       | ((par31 ^ uhi) & SGNM));            \
    vn[ilo##S] = tlo + cwlo;                                                 \
    vn[ihi##S] = thi + cwhi;                                                 \
    /* per-lane 1-byte state store (32 B per warp, coalesced) */             \
    const unsigned flo = (__float_as_uint(cwlo) >> 31);                      \
    const unsigned fhi = (__float_as_uint(cwhi) >> 31);                      \
    g_s[(cn##S * BB + batch) * 8 + li] =                                     \
        (unsigned char)(flo | (fhi << 1) | (eqlo << 2) | (eqhi << 3));       \
    if (li == 0)                                                             \
        g_m[cn##S * BB + batch] =                                            \
            make_uint2(__float_as_uint(m1c), __float_as_uint(m2c));          \
    __syncwarp();                                                            \
} while (0)

__global__ __launch_bounds__(64)
void ldpc_layered_ms_kernel(const float* __restrict__ llr,
                            const int*   __restrict__ H,
                            const int*   __restrict__ iters_p,
                            const int*   __restrict__ cn_order,
                            float*       __restrict__ out)
{
    __shared__ float sh_vn[BPB * STRIDE];

    const int tid   = threadIdx.x;              // 0..63
    const int lane  = tid & 31;
    const int li    = lane & 7;                 // lane within 8-lane group
    const int sh    = lane & 24;                // group's bit offset in ballots
    const int g     = tid >> 3;                 // local batch 0..7
    const int batch = blockIdx.x * BPB + g;

    float* vn = sh_vn + g * STRIDE;

    // Load channel LLRs (float4 per lane; 8 lanes cover 32 floats per pass).
    const float4* src = (const float4*)(llr + (size_t)batch * NN);
    #pragma unroll 4
    for (int k = li; k < NN / 4; k += 8) {
        const float4 v = __ldg(src + k);
        vn[4*k + 0] = v.x;  vn[4*k + 1] = v.y;
        vn[4*k + 2] = v.z;  vn[4*k + 3] = v.w;
    }
    __syncwarp();

    const int iters = *iters_p;
    const int total = iters * MM;               // 2560, even

    // ---- 2-deep software pipeline ----
    int cnA, cnB, iloA, ihiA, iloB, ihiB;
    float cloA, chiA, cloB, chiB;
    int tm = 0;
    PREFETCH(A, 0);
    PREFETCH(B, 1);

    for (int t = 0; t < total; t += 2) {
        STEP(A); PREFETCH(A, t + 2);   // cn_{t+2} distinct in window: safe vs stores
        STEP(B); PREFETCH(B, t + 3);
    }

    // Hard decision output.
    float4* dst = (float4*)(out + (size_t)batch * NN);
    #pragma unroll 4
    for (int k = li; k < NN / 4; k += 8) {
        float4 r;
        r.x = (vn[4*k + 0] < 0.f) ? 1.f : 0.f;
        r.y = (vn[4*k + 1] < 0.f) ? 1.f : 0.f;
        r.z = (vn[4*k + 2] < 0.f) ? 1.f : 0.f;
        r.w = (vn[4*k + 3] < 0.f) ? 1.f : 0.f;
        dst[k] = r;
    }
}

extern "C" void kernel_launch(void* const* d_in, const int* in_sizes, int n_in,
                              void* d_out, int out_size)
{
    const float* llr      = (const float*)d_in[0];   // channel_llr [4096,1024] f32
    const int*   H        = (const int*)  d_in[1];   // H_compact   [512,16]    i32
    const int*   iters_p  = (const int*)  d_in[2];   // iters scalar
    const int*   cn_order = (const int*)  d_in[3];   // cn_order    [512]       i32
    float*       out      = (float*)d_out;

    (void)in_sizes; (void)n_in; (void)out_size;

    ldpc_layered_ms_kernel<<<BB / BPB, 64>>>(llr, H, iters_p, cn_order, out);
}